// round 16
// baseline (speedup 1.0000x reference)
#include <cuda_runtime.h>
#include <cuda_fp16.h>

// Sequence_53300544143404 R15: layer-split warp pairs — zero exchange traffic.
// Warps 0-12: layer1 tiles (16 gate rows, full K=64); warps 13-25: layer2
// (full K=112). Accumulators complete per warp -> warp-private f32 G tile,
// __syncwarp, own pw. One CTA barrier per teacher step. Head + x staging on
// warp 12 (program-ordered with its own col-51 write). fp16 weights/states,
// tanh.approx, pipelined teacher loop + sequential feedback epilogue.
// 128 CTAs x 832 threads.

#define Hh    51
#define T_IN  1000
#define T_TOT 1100
#define NW1   13
#define NWARP 26
#define NTHR  832
#define NCTA  128
#define SD1   72    // B1 row stride (halves): conflict-free (4g+q)
#define SD2   120   // B2 row stride (halves): conflict-free (28g+q)

struct S {
    __half B1[2][32][SD1];    // [pp][n][k] k:0..50 h1, 51 x, rest 0
    __half B2[2][32][SD2];    // k:0..50 h1new, 51 zero, 52..102 h2, rest 0
    float  G[NWARP][16][36];  // warp-private gate tiles (col-parity swizzled)
    float  PH[2][NW1][32];    // double-buffered W_lin partials (L2 warps)
};
#define SMEM_TOTAL ((int)sizeof(S))

#define MMA_F16(d0,d1,d2,d3, a0,a1,a2,a3, b0,b1) \
    asm volatile("mma.sync.aligned.m16n8k16.row.col.f32.f16.f16.f32 " \
        "{%0,%1,%2,%3}, {%4,%5,%6,%7}, {%8,%9}, {%0,%1,%2,%3};" \
        : "+f"(d0),"+f"(d1),"+f"(d2),"+f"(d3) \
        : "r"(a0),"r"(a1),"r"(a2),"r"(a3), "r"(b0),"r"(b1))

__device__ __forceinline__ float tanhA(float x) {
    float r; asm("tanh.approx.f32 %0, %1;" : "=f"(r) : "f"(x)); return r;
}
__device__ __forceinline__ float sigA(float x) {
    return fmaf(tanhA(0.5f * x), 0.5f, 0.5f);
}
__device__ __forceinline__ unsigned mkh2(float v0, float v1) {
    __half h0 = __float2half(v0), h1 = __float2half(v1);
    return (unsigned)__half_as_ushort(h0) | ((unsigned)__half_as_ushort(h1) << 16);
}
__device__ __forceinline__ float wf1(const float* Wih1, const float* Whh1, int R, int k) {
    int h = R >> 2, g = R & 3;
    if (h >= Hh) return 0.f;
    if (k < Hh)  return Whh1[(g * Hh + h) * Hh + k];
    if (k == Hh) return Wih1[g * Hh + h];
    return 0.f;
}
__device__ __forceinline__ float wf2(const float* Wih2, const float* Whh2, int R, int k) {
    int h = R >> 2, g = R & 3;
    if (h >= Hh) return 0.f;
    if (k < Hh) return Wih2[(g * Hh + h) * Hh + k];
    if (k >= 52 && k < 52 + Hh) return Whh2[(g * Hh + h) * Hh + (k - 52)];
    return 0.f;
}
__device__ __forceinline__ float bias_(const float* bi, const float* bh, int R) {
    int h = R >> 2, g = R & 3;
    if (h >= Hh) return 0.f;
    return bi[g * Hh + h] + bh[g * Hh + h];
}

extern __shared__ __align__(16) char smem_raw[];

__global__ __launch_bounds__(NTHR, 1)
void lstm_mma_kernel(const float* __restrict__ xin,
                     const float* __restrict__ W_ih1, const float* __restrict__ W_hh1,
                     const float* __restrict__ b_ih1, const float* __restrict__ b_hh1,
                     const float* __restrict__ W_ih2, const float* __restrict__ W_hh2,
                     const float* __restrict__ b_ih2, const float* __restrict__ b_hh2,
                     const float* __restrict__ W_lin, const float* __restrict__ b_lin,
                     float* __restrict__ out)
{
    S* s = reinterpret_cast<S*>(smem_raw);
    const int tid  = threadIdx.x;
    const int lane = tid & 31;
    const int w    = tid >> 5;
    const bool isL1 = (w < NW1);
    const int wl   = isL1 ? w : w - NW1;   // weight-tile index 0..12
    const int g    = lane >> 2;            // mma groupID 0..7
    const int q2   = (lane & 3) * 2;
    const int sw   = g & 1;                // G column-parity swizzle

    for (int i = tid; i < (int)(sizeof(s->B1) + sizeof(s->B2)) / 4; i += NTHR)
        reinterpret_cast<unsigned*>(s->B1)[i] = 0u;

    // A fragments (fp16, full K for my layer)
    const int R0 = 16 * wl + g, R1 = R0 + 8;
    unsigned A[7][4];
    float bR0, bR1;
    if (isL1) {
        #pragma unroll
        for (int kc = 0; kc < 4; ++kc) {
            int kb = kc * 16 + q2;
            A[kc][0] = mkh2(wf1(W_ih1,W_hh1,R0,kb),   wf1(W_ih1,W_hh1,R0,kb+1));
            A[kc][1] = mkh2(wf1(W_ih1,W_hh1,R1,kb),   wf1(W_ih1,W_hh1,R1,kb+1));
            A[kc][2] = mkh2(wf1(W_ih1,W_hh1,R0,kb+8), wf1(W_ih1,W_hh1,R0,kb+9));
            A[kc][3] = mkh2(wf1(W_ih1,W_hh1,R1,kb+8), wf1(W_ih1,W_hh1,R1,kb+9));
        }
        bR0 = bias_(b_ih1, b_hh1, R0); bR1 = bias_(b_ih1, b_hh1, R1);
    } else {
        #pragma unroll
        for (int kc = 0; kc < 7; ++kc) {
            int kb = kc * 16 + q2;
            A[kc][0] = mkh2(wf2(W_ih2,W_hh2,R0,kb),   wf2(W_ih2,W_hh2,R0,kb+1));
            A[kc][1] = mkh2(wf2(W_ih2,W_hh2,R1,kb),   wf2(W_ih2,W_hh2,R1,kb+1));
            A[kc][2] = mkh2(wf2(W_ih2,W_hh2,R0,kb+8), wf2(W_ih2,W_hh2,R0,kb+9));
            A[kc][3] = mkh2(wf2(W_ih2,W_hh2,R1,kb+8), wf2(W_ih2,W_hh2,R1,kb+9));
        }
        bR0 = bias_(b_ih2, b_hh2, R0); bR1 = bias_(b_ih2, b_hh2, R1);
    }

    // pointwise role: my 4 h = 4wl..4wl+3, n = lane
    const int cb = 4 * wl;
    float wl_[4];
    #pragma unroll
    for (int j = 0; j < 4; ++j)
        wl_[j] = (cb + j < Hh) ? W_lin[cb + j] : 0.f;
    float c_[4] = {};

    const int grow = blockIdx.x * 32 + lane;
    const bool hd = (w == 12);   // head + x-stager warp (L1, owns col 48..51)
    float xv = 0.f, blin = 0.f;
    if (hd) {
        blin = b_lin[0];
        s->B1[0][lane][Hh] = __float2half(xin[grow * T_IN]);
        xv = xin[grow * T_IN + 1];
    }

    // ---- phase helpers ----
    auto mma_l1 = [&](int pb) {
        #pragma unroll
        for (int nt = 0; nt < 4; ++nt) {
            float d0 = bR0, d1 = bR0, d2 = bR1, d3 = bR1;
            #pragma unroll
            for (int kc = 0; kc < 4; ++kc) {
                const __half* bp = &s->B1[pb][nt * 8 + g][kc * 16 + q2];
                unsigned b0 = *reinterpret_cast<const unsigned*>(bp);
                unsigned b1 = *reinterpret_cast<const unsigned*>(bp + 8);
                MMA_F16(d0,d1,d2,d3, A[kc][0],A[kc][1],A[kc][2],A[kc][3], b0,b1);
            }
            int c0 = nt * 8 + q2;
            s->G[w][g][c0 + sw] = d0;     s->G[w][g][c0 + 1 - sw] = d1;
            s->G[w][g + 8][c0 + sw] = d2; s->G[w][g + 8][c0 + 1 - sw] = d3;
        }
    };
    auto mma_l2 = [&](int pb) {
        #pragma unroll
        for (int nt = 0; nt < 4; ++nt) {
            float d0 = bR0, d1 = bR0, d2 = bR1, d3 = bR1;
            #pragma unroll
            for (int kc = 0; kc < 7; ++kc) {
                const __half* bp = &s->B2[pb][nt * 8 + g][kc * 16 + q2];
                unsigned b0 = *reinterpret_cast<const unsigned*>(bp);
                unsigned b1 = *reinterpret_cast<const unsigned*>(bp + 8);
                MMA_F16(d0,d1,d2,d3, A[kc][0],A[kc][1],A[kc][2],A[kc][3], b0,b1);
            }
            int c0 = nt * 8 + q2;
            s->G[w][g][c0 + sw] = d0;     s->G[w][g][c0 + 1 - sw] = d1;
            s->G[w][g + 8][c0 + sw] = d2; s->G[w][g + 8][c0 + 1 - sw] = d3;
        }
    };
    auto pw_l1 = [&](int pbB1, int pbB2) {
        float hv[4];
        #pragma unroll
        for (int j = 0; j < 4; ++j) {
            float gi = s->G[w][4*j+0][lane];
            float gf = s->G[w][4*j+1][lane ^ 1];
            float gg = s->G[w][4*j+2][lane];
            float go = s->G[w][4*j+3][lane ^ 1];
            float cn = sigA(gf) * c_[j] + sigA(gi) * tanhA(gg);
            c_[j] = cn;
            hv[j] = sigA(go) * tanhA(cn);
        }
        uint2 u = make_uint2(mkh2(hv[0], hv[1]), mkh2(hv[2], hv[3]));
        // (warp 12 writes col 51 = 0 here; its own stage_x overwrites after)
        *reinterpret_cast<uint2*>(&s->B1[pbB1][lane][cb]) = u;
        *reinterpret_cast<uint2*>(&s->B2[pbB2][lane][cb]) = u;
    };
    auto pw_l2 = [&](int pbB2, int php) {
        float hv[4];
        #pragma unroll
        for (int j = 0; j < 4; ++j) {
            float gi = s->G[w][4*j+0][lane];
            float gf = s->G[w][4*j+1][lane ^ 1];
            float gg = s->G[w][4*j+2][lane];
            float go = s->G[w][4*j+3][lane ^ 1];
            float cn = sigA(gf) * c_[j] + sigA(gi) * tanhA(gg);
            c_[j] = cn;
            hv[j] = sigA(go) * tanhA(cn);
        }
        uint2 u = make_uint2(mkh2(hv[0], hv[1]), mkh2(hv[2], hv[3]));
        *reinterpret_cast<uint2*>(&s->B2[pbB2][lane][52 + cb]) = u;
        s->PH[php][wl][lane] = wl_[0]*hv[0] + wl_[1]*hv[1] + wl_[2]*hv[2] + wl_[3]*hv[3];
    };
    auto do_head = [&](int php, int tt) -> float {
        float o = blin;
        #pragma unroll
        for (int ww = 0; ww < NW1; ++ww) o += s->PH[php][ww][lane];
        out[grow * T_TOT + tt] = o;
        return o;
    };
    auto stage_x = [&](int pb, float xs) {
        s->B1[pb][lane][Hh] = __float2half(xs);
    };

    __syncthreads();

    // ---- prologue: layer1 of step 0; stage x(1) ----
    if (isL1) {
        mma_l1(0);
        __syncwarp();
        pw_l1(1, 0);
        if (hd) { stage_x(1, xv); xv = xin[grow * T_IN + 2]; }
    }
    __syncthreads();

    // ---- pipelined teacher loop: t = 0 .. T_IN-2 ----
    for (int t = 0; t < T_IN - 1; ++t) {
        const int p = t & 1;
        if (isL1) {
            mma_l1(p ^ 1);          // layer1 of step t+1
            __syncwarp();
            pw_l1(p, p ^ 1);        // h1new(t+1) -> B1[p], B2[p^1]
            if (hd) {
                if (t >= 1) do_head(p ^ 1, t - 1);
                if (t + 2 < T_IN) {
                    stage_x(p, xv);
                    if (t + 3 < T_IN) xv = xin[grow * T_IN + t + 3];
                }
            }
        } else {
            mma_l2(p);              // layer2 of step t
            __syncwarp();
            pw_l2(p ^ 1, p);        // h2new(t) -> B2[p^1]; PH[p]
        }
        __syncthreads();
    }

    // ---- sequential feedback epilogue: t = T_IN-1 .. T_TOT-1 ----
    for (int t = T_IN - 1; t < T_TOT; ++t) {
        const int p = t & 1;
        if (!isL1) {
            mma_l2(p);
            __syncwarp();
            pw_l2(p ^ 1, p);
        }
        __syncthreads();
        if (hd) {
            if (t == T_IN - 1) do_head(p ^ 1, t - 1);   // pending out(T_IN-2)
            float o = do_head(p, t);
            if (t + 1 < T_TOT) stage_x(p ^ 1, o);       // x(t+1) = out(t)
        }
        __syncthreads();
        if (t + 1 < T_TOT) {
            if (isL1) {
                mma_l1(p ^ 1);
                __syncwarp();
                pw_l1(p, p ^ 1);
            }
            __syncthreads();
        }
    }
}

extern "C" void kernel_launch(void* const* d_in, const int* in_sizes, int n_in,
                              void* d_out, int out_size) {
    (void)in_sizes; (void)n_in; (void)out_size;
    cudaFuncSetAttribute(lstm_mma_kernel, cudaFuncAttributeMaxDynamicSharedMemorySize, SMEM_TOTAL);
    lstm_mma_kernel<<<NCTA, NTHR, SMEM_TOTAL>>>(
        (const float*)d_in[0],   // inputs [B, T]
        (const float*)d_in[1],   // W_ih1 [204,1]
        (const float*)d_in[2],   // W_hh1 [204,51]
        (const float*)d_in[3],   // b_ih1 [204]
        (const float*)d_in[4],   // b_hh1 [204]
        (const float*)d_in[5],   // W_ih2 [204,51]
        (const float*)d_in[6],   // W_hh2 [204,51]
        (const float*)d_in[7],   // b_ih2 [204]
        (const float*)d_in[8],   // b_hh2 [204]
        (const float*)d_in[9],   // W_lin [1,51]
        (const float*)d_in[10],  // b_lin [1]
        (float*)d_out);          // out [B, 1100]
}